// round 14
// baseline (speedup 1.0000x reference)
#include <cuda_runtime.h>

#define BB 64
#define HH 56
#define WW 56
#define CC 256
#define COUT 64
#define ROUTES 4
#define RW (CC / ROUTES)          // 64 channels per route
#define RCHUNKS 14                // 4 rows per chunk
#define SLOTS 9                   // 3x3 (dh,dw) classes
#define NQ (SLOTS * CC / 4)       // 576 float4 quads in a full patch sum

// composed routing weights: W2[i][r] = (conv_w @ fc_w)[i][r] / 729   (2304 x 4)
__device__ float g_W2[SLOTS * CC * ROUTES];
__device__ float g_C[ROUTES];               // c[r] = conv_b @ fc_w + fc_b
__device__ float g_logits[BB * ROUTES];     // atomic partial logits (K0 zeroes)

__device__ __forceinline__ float4 f4add(float4 a, float4 b) {
    return make_float4(a.x + b.x, a.y + b.y, a.z + b.z, a.w + b.w);
}
__device__ __forceinline__ float4 f4sub(float4 a, float4 b) {
    return make_float4(a.x - b.x, a.y - b.y, a.z - b.z, a.w - b.w);
}
__device__ __forceinline__ float4 f4fma(float s, float4 w, float4 acc) {
    return make_float4(fmaf(s, w.x, acc.x), fmaf(s, w.y, acc.y),
                       fmaf(s, w.z, acc.z), fmaf(s, w.w, acc.w));
}

// ---------------------------------------------------------------------------
// K0 (tiny, runs BEFORE the stream -> launch order is the dependency):
// compose W2 = (conv_w @ fc_w)/729 and C = conv_b@fc_w + fc_b, and zero the
// atomic logit accumulators for this graph replay.
// 64 blocks x 256 threads; block b computes W2 rows [b*36, (b+1)*36).
// ---------------------------------------------------------------------------
__global__ __launch_bounds__(256) void compose_w2_kernel(const float* __restrict__ conv_w,
                                                         const float* __restrict__ conv_b,
                                                         const float* __restrict__ fc_w,
                                                         const float* __restrict__ fc_b) {
    const int b   = blockIdx.x;
    const int tid = threadIdx.x;

    if (tid < 144) {
        const int i = b * 36 + (tid >> 2);
        const int r = tid & 3;
        float s = 0.f;
#pragma unroll 16
        for (int o = 0; o < COUT; o++)
            s = fmaf(conv_w[(size_t)i * COUT + o], fc_w[o * ROUTES + r], s);
        g_W2[i * ROUTES + r] = s * (1.0f / 729.0f);
    }
    if (b == 0) {
        if (tid >= 160 && tid < 160 + ROUTES) {
            const int r = tid - 160;
            float s = fc_b[r];
            for (int o = 0; o < COUT; o++)
                s = fmaf(conv_b[o], fc_w[o * ROUTES + r], s);
            g_C[r] = s;
        }
        // zero atomic accumulators (BB*ROUTES = 256 floats)
        g_logits[tid] = 0.f;
    }
}

// ---------------------------------------------------------------------------
// K1: streaming patch-sum + in-block logit dot. Block = (batch, 4-row chunk),
// 256 threads = 64 channel-quads x 4 row-threads. Each row-thread owns one
// row: even/odd running float4 sums + edge captures -> 3 dw-class sums.
// Reducer lanes (rt==0) apply h-parity/boundary logic -> 9-slot partial in
// SMEM. Then ALL 256 threads dot the partial against W2 (L2-resident) and
// thread 0 atomicAdds 4 partial logits. No global scratch at all.
// ---------------------------------------------------------------------------
__global__ __launch_bounds__(256) void patch_logits_kernel(const float* __restrict__ in) {
    const int b     = blockIdx.x;
    const int chunk = blockIdx.y;          // 0..13
    const int tid   = threadIdx.x;
    const int q     = tid & 63;            // channel quad 0..63
    const int rt    = tid >> 6;            // row-thread 0..3
    const int h     = chunk * 4 + rt;

    const float4* row = (const float4*)in
                      + ((size_t)(b * HH + h) * WW) * (CC / 4) + q;

    float4 e = make_float4(0.f, 0.f, 0.f, 0.f);
    float4 o = make_float4(0.f, 0.f, 0.f, 0.f);
    float4 v0, v54, v55;
#pragma unroll
    for (int w = 0; w < WW; w += 2) {
        float4 a  = row[(size_t)w * (CC / 4)];
        float4 bb = row[(size_t)(w + 1) * (CC / 4)];
        if (w == 0)  { v0 = a; }
        if (w == 54) { v54 = a; v55 = bb; }
        e = f4add(e, a);
        o = f4add(o, bb);
    }

    __shared__ float4 sacc[4][3][64];
    sacc[rt][0][q] = f4sub(e, v54);  // W0: even w in [0,52]
    sacc[rt][1][q] = f4sub(o, v55);  // W1: odd  w in [1,53]
    sacc[rt][2][q] = f4sub(e, v0);   // W2: even w in [2,54]
    __syncthreads();

    __shared__ float4 sS4[SLOTS][64];     // 9-slot chunk partial (9 KB)
    if (rt == 0) {
        float4 outv[SLOTS];
#pragma unroll
        for (int s = 0; s < SLOTS; s++) outv[s] = make_float4(0.f, 0.f, 0.f, 0.f);

#pragma unroll
        for (int r = 0; r < 4; r++) {
            const int hh = chunk * 4 + r;
            const float4 W0 = sacc[r][0][q];
            const float4 W1 = sacc[r][1][q];
            const float4 W2 = sacc[r][2][q];
            if ((hh & 1) == 0) {
                if (hh <= 52) { outv[0] = f4add(outv[0], W0); outv[1] = f4add(outv[1], W1); outv[2] = f4add(outv[2], W2); }
                if (hh >= 2)  { outv[6] = f4add(outv[6], W0); outv[7] = f4add(outv[7], W1); outv[8] = f4add(outv[8], W2); }
            } else {
                if (hh <= 53) { outv[3] = f4add(outv[3], W0); outv[4] = f4add(outv[4], W1); outv[5] = f4add(outv[5], W2); }
            }
        }
#pragma unroll
        for (int s = 0; s < SLOTS; s++) sS4[s][q] = outv[s];
    }
    __syncthreads();

    // ---- dot chunk partial against W2 -> 4 partial logits ------------------
    float4 acc = make_float4(0.f, 0.f, 0.f, 0.f);
    for (int i4 = tid; i4 < NQ; i4 += 256) {
        const float4 s = sS4[i4 >> 6][i4 & 63];
        const float4* w2 = (const float4*)g_W2 + i4 * 4;   // rows 4*i4..4*i4+3
        acc = f4fma(s.x, w2[0], acc);
        acc = f4fma(s.y, w2[1], acc);
        acc = f4fma(s.z, w2[2], acc);
        acc = f4fma(s.w, w2[3], acc);
    }

#pragma unroll
    for (int off = 16; off > 0; off >>= 1) {
        acc.x += __shfl_xor_sync(0xFFFFFFFFu, acc.x, off);
        acc.y += __shfl_xor_sync(0xFFFFFFFFu, acc.y, off);
        acc.z += __shfl_xor_sync(0xFFFFFFFFu, acc.z, off);
        acc.w += __shfl_xor_sync(0xFFFFFFFFu, acc.w, off);
    }

    __shared__ float4 wred[8];
    if ((tid & 31) == 0) wred[tid >> 5] = acc;
    __syncthreads();

    if (tid == 0) {
        float4 tot = wred[0];
#pragma unroll
        for (int wg = 1; wg < 8; wg++) tot = f4add(tot, wred[wg]);
        atomicAdd(&g_logits[b * ROUTES + 0], tot.x);
        atomicAdd(&g_logits[b * ROUTES + 1], tot.y);
        atomicAdd(&g_logits[b * ROUTES + 2], tot.z);
        atomicAdd(&g_logits[b * ROUTES + 3], tot.w);
    }
}

// ---------------------------------------------------------------------------
// K3: routed channel-group gather with inline argmax. Block = (batch,
// 64-pixel tile). Thread 0 reads the 4 accumulated logits, adds C, argmaxes.
// Tile 0 also writes out_logits. 128 threads x 8 independent float4 copies.
// ---------------------------------------------------------------------------
__global__ __launch_bounds__(128) void gather_kernel(const float4* __restrict__ in4,
                                                     float4* __restrict__ out4,
                                                     float* __restrict__ out_logits) {
    const int b = blockIdx.x;
    const int t = threadIdx.x;

    __shared__ int s_route;
    if (t == 0) {
        float l0 = g_logits[b * ROUTES + 0] + g_C[0];
        float l1 = g_logits[b * ROUTES + 1] + g_C[1];
        float l2 = g_logits[b * ROUTES + 2] + g_C[2];
        float l3 = g_logits[b * ROUTES + 3] + g_C[3];
        float best = l0; int br = 0;
        if (l1 > best) { best = l1; br = 1; }
        if (l2 > best) { best = l2; br = 2; }
        if (l3 > best) { best = l3; br = 3; }      // first-max == argmax
        s_route = br;
        if (blockIdx.y == 0) {
            out_logits[b * ROUTES + 0] = l0;
            out_logits[b * ROUTES + 1] = l1;
            out_logits[b * ROUTES + 2] = l2;
            out_logits[b * ROUTES + 3] = l3;
        }
    }
    __syncthreads();
    const int r = s_route;

    const size_t base_pix = (size_t)b * (HH * WW) + (size_t)blockIdx.y * 64;
    const float4* src = in4 + base_pix * (CC / 4) + r * (RW / 4);
    float4* dst = out4 + base_pix * (RW / 4);

#pragma unroll
    for (int k = 0; k < 8; k++) {
        const int item = t + k * 128;      // 0..1023 = 64 pixels x 16 float4
        const int p = item >> 4;
        const int j = item & 15;
        dst[item] = src[(size_t)p * (CC / 4) + j];
    }
}

// ---------------------------------------------------------------------------
extern "C" void kernel_launch(void* const* d_in, const int* in_sizes, int n_in,
                              void* d_out, int out_size) {
    const float* in     = (const float*)d_in[0];
    const float* conv_w = (const float*)d_in[1];
    const float* conv_b = (const float*)d_in[2];
    const float* fc_w   = (const float*)d_in[3];
    const float* fc_b   = (const float*)d_in[4];

    float* out        = (float*)d_out;
    float* out_logits = out + (size_t)BB * HH * WW * RW;  // x first, then logits

    compose_w2_kernel<<<BB, 256>>>(conv_w, conv_b, fc_w, fc_b);
    patch_logits_kernel<<<dim3(BB, RCHUNKS), 256>>>(in);
    gather_kernel<<<dim3(BB, HH * WW / 64), 128>>>((const float4*)in, (float4*)out,
                                                   out_logits);
}

// round 15
// speedup vs baseline: 1.0214x; 1.0214x over previous
#include <cuda_runtime.h>

#define BB 64
#define HH 56
#define WW 56
#define CC 256
#define COUT 64
#define ROUTES 4
#define RW (CC / ROUTES)          // 64 channels per route
#define RCHUNKS 14                // 4 rows per chunk
#define SLOTS 9                   // 3x3 (dh,dw) classes
#define NQ (SLOTS * CC / 4)       // 576 float4 quads in a full patch sum
#define W2ROWS (SLOTS * CC)       // 2304

// composed routing weights: W2[i][r] = (conv_w @ fc_w)[i][r] / 729   (2304 x 4)
__device__ float g_W2[W2ROWS * ROUTES];
__device__ float g_C[ROUTES];               // c[r] = conv_b @ fc_w + fc_b
__device__ float g_logits[BB * ROUTES];     // atomic partial logits (K0 zeroes)

__device__ __forceinline__ float4 f4add(float4 a, float4 b) {
    return make_float4(a.x + b.x, a.y + b.y, a.z + b.z, a.w + b.w);
}
__device__ __forceinline__ float4 f4sub(float4 a, float4 b) {
    return make_float4(a.x - b.x, a.y - b.y, a.z - b.z, a.w - b.w);
}
__device__ __forceinline__ float4 f4fma(float s, float4 w, float4 acc) {
    return make_float4(fmaf(s, w.x, acc.x), fmaf(s, w.y, acc.y),
                       fmaf(s, w.z, acc.z), fmaf(s, w.w, acc.w));
}

// ---------------------------------------------------------------------------
// K0 (fast, runs BEFORE the stream -> launch order is the dependency):
// warp-per-row W2 composition. 288 blocks x 8 warps; warp w of block b owns
// row i = b*8+w. Each lane: 2 coalesced conv_w loads; 4 values reduced by
// warp shuffles -> one float4 store. No serial chains (the R14 K0 was a
// 64-deep fmaf chain at occ 8.5% costing 6.8us).
// Block 0 also zeroes the atomic logit accumulators and computes C.
// ---------------------------------------------------------------------------
__global__ __launch_bounds__(256) void compose_w2_kernel(const float* __restrict__ conv_w,
                                                         const float* __restrict__ conv_b,
                                                         const float* __restrict__ fc_w,
                                                         const float* __restrict__ fc_b) {
    const int tid  = threadIdx.x;
    const int warp = tid >> 5;
    const int lane = tid & 31;

    __shared__ float sfc[COUT * ROUTES];
    if (tid < COUT * ROUTES) sfc[tid] = fc_w[tid];
    __syncthreads();

    const int i = blockIdx.x * 8 + warp;            // W2 row 0..2303
    const float a = conv_w[(size_t)i * COUT + lane];
    const float b = conv_w[(size_t)i * COUT + 32 + lane];

    float4 p;
    p.x = fmaf(a, sfc[lane * 4 + 0], b * sfc[(lane + 32) * 4 + 0]);
    p.y = fmaf(a, sfc[lane * 4 + 1], b * sfc[(lane + 32) * 4 + 1]);
    p.z = fmaf(a, sfc[lane * 4 + 2], b * sfc[(lane + 32) * 4 + 2]);
    p.w = fmaf(a, sfc[lane * 4 + 3], b * sfc[(lane + 32) * 4 + 3]);

#pragma unroll
    for (int off = 16; off > 0; off >>= 1) {
        p.x += __shfl_xor_sync(0xFFFFFFFFu, p.x, off);
        p.y += __shfl_xor_sync(0xFFFFFFFFu, p.y, off);
        p.z += __shfl_xor_sync(0xFFFFFFFFu, p.z, off);
        p.w += __shfl_xor_sync(0xFFFFFFFFu, p.w, off);
    }

    if (lane == 0) {
        const float inv = 1.0f / 729.0f;
        ((float4*)g_W2)[i] = make_float4(p.x * inv, p.y * inv, p.z * inv, p.w * inv);
    }

    if (blockIdx.x == 0) {
        g_logits[tid] = 0.f;                        // BB*ROUTES = 256 floats
        if (tid < ROUTES) {
            float s = fc_b[tid];
#pragma unroll 16
            for (int o = 0; o < COUT; o++)
                s = fmaf(conv_b[o], sfc[o * ROUTES + tid], s);
            g_C[tid] = s;
        }
    }
}

// ---------------------------------------------------------------------------
// K1: streaming patch-sum + in-block logit dot. Block = (batch, 4-row chunk),
// 256 threads = 64 channel-quads x 4 row-threads. Each row-thread owns one
// row: even/odd running float4 sums + edge captures -> 3 dw-class sums.
// Reducer lanes (rt==0) apply h-parity/boundary logic -> 9-slot partial in
// SMEM. Then ALL 256 threads dot the partial against W2 (L2-resident) and
// thread 0 atomicAdds 4 partial logits. No global scratch at all.
// ---------------------------------------------------------------------------
__global__ __launch_bounds__(256) void patch_logits_kernel(const float* __restrict__ in) {
    const int b     = blockIdx.x;
    const int chunk = blockIdx.y;          // 0..13
    const int tid   = threadIdx.x;
    const int q     = tid & 63;            // channel quad 0..63
    const int rt    = tid >> 6;            // row-thread 0..3
    const int h     = chunk * 4 + rt;

    const float4* row = (const float4*)in
                      + ((size_t)(b * HH + h) * WW) * (CC / 4) + q;

    float4 e = make_float4(0.f, 0.f, 0.f, 0.f);
    float4 o = make_float4(0.f, 0.f, 0.f, 0.f);
    float4 v0, v54, v55;
#pragma unroll
    for (int w = 0; w < WW; w += 2) {
        float4 a  = row[(size_t)w * (CC / 4)];
        float4 bb = row[(size_t)(w + 1) * (CC / 4)];
        if (w == 0)  { v0 = a; }
        if (w == 54) { v54 = a; v55 = bb; }
        e = f4add(e, a);
        o = f4add(o, bb);
    }

    __shared__ float4 sacc[4][3][64];
    sacc[rt][0][q] = f4sub(e, v54);  // W0: even w in [0,52]
    sacc[rt][1][q] = f4sub(o, v55);  // W1: odd  w in [1,53]
    sacc[rt][2][q] = f4sub(e, v0);   // W2: even w in [2,54]
    __syncthreads();

    __shared__ float4 sS4[SLOTS][64];     // 9-slot chunk partial (9 KB)
    if (rt == 0) {
        float4 outv[SLOTS];
#pragma unroll
        for (int s = 0; s < SLOTS; s++) outv[s] = make_float4(0.f, 0.f, 0.f, 0.f);

#pragma unroll
        for (int r = 0; r < 4; r++) {
            const int hh = chunk * 4 + r;
            const float4 W0 = sacc[r][0][q];
            const float4 W1 = sacc[r][1][q];
            const float4 W2 = sacc[r][2][q];
            if ((hh & 1) == 0) {
                if (hh <= 52) { outv[0] = f4add(outv[0], W0); outv[1] = f4add(outv[1], W1); outv[2] = f4add(outv[2], W2); }
                if (hh >= 2)  { outv[6] = f4add(outv[6], W0); outv[7] = f4add(outv[7], W1); outv[8] = f4add(outv[8], W2); }
            } else {
                if (hh <= 53) { outv[3] = f4add(outv[3], W0); outv[4] = f4add(outv[4], W1); outv[5] = f4add(outv[5], W2); }
            }
        }
#pragma unroll
        for (int s = 0; s < SLOTS; s++) sS4[s][q] = outv[s];
    }
    __syncthreads();

    // ---- dot chunk partial against W2 -> 4 partial logits ------------------
    float4 acc = make_float4(0.f, 0.f, 0.f, 0.f);
    for (int i4 = tid; i4 < NQ; i4 += 256) {
        const float4 s = sS4[i4 >> 6][i4 & 63];
        const float4* w2 = (const float4*)g_W2 + i4 * 4;   // rows 4*i4..4*i4+3
        acc = f4fma(s.x, w2[0], acc);
        acc = f4fma(s.y, w2[1], acc);
        acc = f4fma(s.z, w2[2], acc);
        acc = f4fma(s.w, w2[3], acc);
    }

#pragma unroll
    for (int off = 16; off > 0; off >>= 1) {
        acc.x += __shfl_xor_sync(0xFFFFFFFFu, acc.x, off);
        acc.y += __shfl_xor_sync(0xFFFFFFFFu, acc.y, off);
        acc.z += __shfl_xor_sync(0xFFFFFFFFu, acc.z, off);
        acc.w += __shfl_xor_sync(0xFFFFFFFFu, acc.w, off);
    }

    __shared__ float4 wred[8];
    if ((tid & 31) == 0) wred[tid >> 5] = acc;
    __syncthreads();

    if (tid == 0) {
        float4 tot = wred[0];
#pragma unroll
        for (int wg = 1; wg < 8; wg++) tot = f4add(tot, wred[wg]);
        atomicAdd(&g_logits[b * ROUTES + 0], tot.x);
        atomicAdd(&g_logits[b * ROUTES + 1], tot.y);
        atomicAdd(&g_logits[b * ROUTES + 2], tot.z);
        atomicAdd(&g_logits[b * ROUTES + 3], tot.w);
    }
}

// ---------------------------------------------------------------------------
// K3: routed channel-group gather with inline argmax. Block = (batch,
// 64-pixel tile). Thread 0 reads the 4 accumulated logits, adds C, argmaxes.
// Tile 0 also writes out_logits. 128 threads x 8 independent float4 copies.
// ---------------------------------------------------------------------------
__global__ __launch_bounds__(128) void gather_kernel(const float4* __restrict__ in4,
                                                     float4* __restrict__ out4,
                                                     float* __restrict__ out_logits) {
    const int b = blockIdx.x;
    const int t = threadIdx.x;

    __shared__ int s_route;
    if (t == 0) {
        float l0 = g_logits[b * ROUTES + 0] + g_C[0];
        float l1 = g_logits[b * ROUTES + 1] + g_C[1];
        float l2 = g_logits[b * ROUTES + 2] + g_C[2];
        float l3 = g_logits[b * ROUTES + 3] + g_C[3];
        float best = l0; int br = 0;
        if (l1 > best) { best = l1; br = 1; }
        if (l2 > best) { best = l2; br = 2; }
        if (l3 > best) { best = l3; br = 3; }      // first-max == argmax
        s_route = br;
        if (blockIdx.y == 0) {
            out_logits[b * ROUTES + 0] = l0;
            out_logits[b * ROUTES + 1] = l1;
            out_logits[b * ROUTES + 2] = l2;
            out_logits[b * ROUTES + 3] = l3;
        }
    }
    __syncthreads();
    const int r = s_route;

    const size_t base_pix = (size_t)b * (HH * WW) + (size_t)blockIdx.y * 64;
    const float4* src = in4 + base_pix * (CC / 4) + r * (RW / 4);
    float4* dst = out4 + base_pix * (RW / 4);

#pragma unroll
    for (int k = 0; k < 8; k++) {
        const int item = t + k * 128;      // 0..1023 = 64 pixels x 16 float4
        const int p = item >> 4;
        const int j = item & 15;
        dst[item] = src[(size_t)p * (CC / 4) + j];
    }
}

// ---------------------------------------------------------------------------
extern "C" void kernel_launch(void* const* d_in, const int* in_sizes, int n_in,
                              void* d_out, int out_size) {
    const float* in     = (const float*)d_in[0];
    const float* conv_w = (const float*)d_in[1];
    const float* conv_b = (const float*)d_in[2];
    const float* fc_w   = (const float*)d_in[3];
    const float* fc_b   = (const float*)d_in[4];

    float* out        = (float*)d_out;
    float* out_logits = out + (size_t)BB * HH * WW * RW;  // x first, then logits

    compose_w2_kernel<<<W2ROWS / 8, 256>>>(conv_w, conv_b, fc_w, fc_b);
    patch_logits_kernel<<<dim3(BB, RCHUNKS), 256>>>(in);
    gather_kernel<<<dim3(BB, HH * WW / 64), 128>>>((const float4*)in, (float4*)out,
                                                   out_logits);
}

// round 16
// speedup vs baseline: 1.0324x; 1.0108x over previous
#include <cuda_runtime.h>

#define BB 64
#define HH 56
#define WW 56
#define CC 256
#define COUT 64
#define ROUTES 4
#define RW (CC / ROUTES)          // 64 channels per route
#define RCHUNKS 14                // 4 rows per chunk
#define SLOTS 9                   // 3x3 (dh,dw) classes
#define NQ (SLOTS * CC / 4)       // 576 float4 quads in a full patch sum
#define W2ROWS (SLOTS * CC)       // 2304
#define NW2B 64                   // W2 composer blocks (bids 0..63, wave 1)
#define NPATCH (BB * RCHUNKS)     // 896 patch blocks (bids 64..959)

// composed routing weights: W2[i][r] = (conv_w @ fc_w)[i][r] / 729   (2304 x 4)
__device__ float g_W2[W2ROWS * ROUTES];
__device__ float g_C[ROUTES];               // c[r] = conv_b @ fc_w + fc_b
__device__ float g_logits[BB * ROUTES];     // atomic partial logits (self-reset)
__device__ int   g_cnt[BB];                 // per-batch patch counters (self-reset)
__device__ int   g_w2cnt;                   // W2 completion counter (self-reset)
__device__ int   g_pcnt;                    // global patch counter (self-reset)
__device__ volatile int g_w2flag;           // W2-ready flag (self-reset)
__device__ int   g_route[BB];

__device__ __forceinline__ float4 f4add(float4 a, float4 b) {
    return make_float4(a.x + b.x, a.y + b.y, a.z + b.z, a.w + b.w);
}
__device__ __forceinline__ float4 f4sub(float4 a, float4 b) {
    return make_float4(a.x - b.x, a.y - b.y, a.z - b.z, a.w - b.w);
}
__device__ __forceinline__ float4 f4fma(float s, float4 w, float4 acc) {
    return make_float4(fmaf(s, w.x, acc.x), fmaf(s, w.y, acc.y),
                       fmaf(s, w.z, acc.z), fmaf(s, w.w, acc.w));
}

// ---------------------------------------------------------------------------
// K1: single launch, 960 blocks.
//  bids 0..63   : W2 composer blocks (wave 1, ~2-3us, fully hidden under the
//                 stream). Block w owns 36 W2 rows, warp-per-row with shuffle
//                 reduction. 64th finisher raises g_w2flag (release).
//  bids 64..959 : patch blocks (b = idx/14 -> batch-contiguous). Stream 4 rows
//                 -> 9-slot partial in SMEM -> dot vs W2 (flag is set long
//                 before any tail arrives) -> atomicAdd 4 partial logits.
//                 LAST block per batch finalizes: +C, argmax -> g_route[b],
//                 out_logits, resets g_logits. Last patch block overall resets
//                 the W2 flag for the next graph replay.
// ---------------------------------------------------------------------------
__global__ __launch_bounds__(256) void patch_route_kernel(const float* __restrict__ in,
                                                          const float* __restrict__ conv_w,
                                                          const float* __restrict__ conv_b,
                                                          const float* __restrict__ fc_w,
                                                          const float* __restrict__ fc_b,
                                                          float* __restrict__ out_logits) {
    const int bid = blockIdx.x;
    const int tid = threadIdx.x;

    if (bid < NW2B) {
        // ================= W2 composer =================
        const int warp = tid >> 5;
        const int lane = tid & 31;

        __shared__ float sfc[COUT * ROUTES];
        if (tid < COUT * ROUTES) sfc[tid] = fc_w[tid];
        __syncthreads();

#pragma unroll
        for (int k = 0; k < 5; k++) {
            const int il = warp + 8 * k;           // 0..39
            if (il < 36) {
                const int i = bid * 36 + il;       // W2 row
                const float a  = conv_w[(size_t)i * COUT + lane];
                const float bb = conv_w[(size_t)i * COUT + 32 + lane];
                float4 p;
                p.x = fmaf(a, sfc[lane * 4 + 0], bb * sfc[(lane + 32) * 4 + 0]);
                p.y = fmaf(a, sfc[lane * 4 + 1], bb * sfc[(lane + 32) * 4 + 1]);
                p.z = fmaf(a, sfc[lane * 4 + 2], bb * sfc[(lane + 32) * 4 + 2]);
                p.w = fmaf(a, sfc[lane * 4 + 3], bb * sfc[(lane + 32) * 4 + 3]);
#pragma unroll
                for (int off = 16; off > 0; off >>= 1) {
                    p.x += __shfl_xor_sync(0xFFFFFFFFu, p.x, off);
                    p.y += __shfl_xor_sync(0xFFFFFFFFu, p.y, off);
                    p.z += __shfl_xor_sync(0xFFFFFFFFu, p.z, off);
                    p.w += __shfl_xor_sync(0xFFFFFFFFu, p.w, off);
                }
                if (lane == 0) {
                    const float inv = 1.0f / 729.0f;
                    ((float4*)g_W2)[i] = make_float4(p.x * inv, p.y * inv,
                                                     p.z * inv, p.w * inv);
                }
            }
        }

        if (bid == 0 && tid < ROUTES) {            // C = conv_b@fc_w + fc_b
            float s = fc_b[tid];
#pragma unroll 16
            for (int o = 0; o < COUT; o++)
                s = fmaf(conv_b[o], sfc[o * ROUTES + tid], s);
            g_C[tid] = s;
        }
        __syncthreads();

        if (tid == 0) {
            __threadfence();                       // publish W2 (+C) stores
            int old = atomicAdd(&g_w2cnt, 1);
            if (old == NW2B - 1) {
                g_w2cnt = 0;                       // reset for next replay
                __threadfence();
                g_w2flag = 1;                      // release
            }
        }
        return;
    }

    // ================= patch block =================
    const int pb    = bid - NW2B;
    const int b     = pb / RCHUNKS;
    const int chunk = pb % RCHUNKS;
    const int q     = tid & 63;            // channel quad 0..63
    const int rt    = tid >> 6;            // row-thread 0..3
    const int h     = chunk * 4 + rt;

    const float4* row = (const float4*)in
                      + ((size_t)(b * HH + h) * WW) * (CC / 4) + q;

    float4 e = make_float4(0.f, 0.f, 0.f, 0.f);
    float4 o = make_float4(0.f, 0.f, 0.f, 0.f);
    float4 v0, v54, v55;
#pragma unroll
    for (int w = 0; w < WW; w += 2) {
        float4 a  = row[(size_t)w * (CC / 4)];
        float4 bb = row[(size_t)(w + 1) * (CC / 4)];
        if (w == 0)  { v0 = a; }
        if (w == 54) { v54 = a; v55 = bb; }
        e = f4add(e, a);
        o = f4add(o, bb);
    }

    __shared__ float4 sacc[4][3][64];
    sacc[rt][0][q] = f4sub(e, v54);  // W0: even w in [0,52]
    sacc[rt][1][q] = f4sub(o, v55);  // W1: odd  w in [1,53]
    sacc[rt][2][q] = f4sub(e, v0);   // W2: even w in [2,54]
    __syncthreads();

    __shared__ float4 sS4[SLOTS][64];     // 9-slot chunk partial (9 KB)
    if (rt == 0) {
        float4 outv[SLOTS];
#pragma unroll
        for (int s = 0; s < SLOTS; s++) outv[s] = make_float4(0.f, 0.f, 0.f, 0.f);

#pragma unroll
        for (int r = 0; r < 4; r++) {
            const int hh = chunk * 4 + r;
            const float4 W0 = sacc[r][0][q];
            const float4 W1 = sacc[r][1][q];
            const float4 W2 = sacc[r][2][q];
            if ((hh & 1) == 0) {
                if (hh <= 52) { outv[0] = f4add(outv[0], W0); outv[1] = f4add(outv[1], W1); outv[2] = f4add(outv[2], W2); }
                if (hh >= 2)  { outv[6] = f4add(outv[6], W0); outv[7] = f4add(outv[7], W1); outv[8] = f4add(outv[8], W2); }
            } else {
                if (hh <= 53) { outv[3] = f4add(outv[3], W0); outv[4] = f4add(outv[4], W1); outv[5] = f4add(outv[5], W2); }
            }
        }
#pragma unroll
        for (int s = 0; s < SLOTS; s++) sS4[s][q] = outv[s];
    }

    // ---- wait for W2 (already set in practice: composers are wave-1) -------
    if (tid == 0) {
        while (g_w2flag == 0) { __nanosleep(64); }
        __threadfence();                           // acquire W2 + C
    }
    __syncthreads();                               // also publishes sS4

    // ---- dot chunk partial against W2 -> 4 partial logits ------------------
    float4 acc = make_float4(0.f, 0.f, 0.f, 0.f);
    for (int i4 = tid; i4 < NQ; i4 += 256) {
        const float4 s = sS4[i4 >> 6][i4 & 63];
        const float4* w2 = (const float4*)g_W2 + i4 * 4;   // rows 4*i4..4*i4+3
        acc = f4fma(s.x, w2[0], acc);
        acc = f4fma(s.y, w2[1], acc);
        acc = f4fma(s.z, w2[2], acc);
        acc = f4fma(s.w, w2[3], acc);
    }

#pragma unroll
    for (int off = 16; off > 0; off >>= 1) {
        acc.x += __shfl_xor_sync(0xFFFFFFFFu, acc.x, off);
        acc.y += __shfl_xor_sync(0xFFFFFFFFu, acc.y, off);
        acc.z += __shfl_xor_sync(0xFFFFFFFFu, acc.z, off);
        acc.w += __shfl_xor_sync(0xFFFFFFFFu, acc.w, off);
    }

    __shared__ float4 wred[8];
    if ((tid & 31) == 0) wred[tid >> 5] = acc;
    __syncthreads();

    __shared__ int s_last;
    if (tid == 0) {
        float4 tot = wred[0];
#pragma unroll
        for (int wg = 1; wg < 8; wg++) tot = f4add(tot, wred[wg]);
        atomicAdd(&g_logits[b * ROUTES + 0], tot.x);
        atomicAdd(&g_logits[b * ROUTES + 1], tot.y);
        atomicAdd(&g_logits[b * ROUTES + 2], tot.z);
        atomicAdd(&g_logits[b * ROUTES + 3], tot.w);
        __threadfence();
        int old = atomicAdd(&g_cnt[b], 1);
        s_last = (old == RCHUNKS - 1);
        if (s_last) g_cnt[b] = 0;                  // reset for next replay
    }
    __syncthreads();

    // ---- last block of batch: finalize logits -> route ---------------------
    if (s_last && tid == 0) {
        __threadfence();                           // acquire sibling atomics
        float l0 = g_logits[b * ROUTES + 0] + g_C[0];
        float l1 = g_logits[b * ROUTES + 1] + g_C[1];
        float l2 = g_logits[b * ROUTES + 2] + g_C[2];
        float l3 = g_logits[b * ROUTES + 3] + g_C[3];
        float best = l0; int br = 0;
        if (l1 > best) { best = l1; br = 1; }
        if (l2 > best) { best = l2; br = 2; }
        if (l3 > best) { best = l3; br = 3; }      // first-max == argmax
        g_route[b] = br;
        out_logits[b * ROUTES + 0] = l0;
        out_logits[b * ROUTES + 1] = l1;
        out_logits[b * ROUTES + 2] = l2;
        out_logits[b * ROUTES + 3] = l3;
        g_logits[b * ROUTES + 0] = 0.f;            // reset for next replay
        g_logits[b * ROUTES + 1] = 0.f;
        g_logits[b * ROUTES + 2] = 0.f;
        g_logits[b * ROUTES + 3] = 0.f;
    }

    // ---- last patch block overall resets the W2 flag ------------------------
    if (tid == 0) {
        int old = atomicAdd(&g_pcnt, 1);
        if (old == NPATCH - 1) {
            g_pcnt = 0;
            g_w2flag = 0;
        }
    }
}

// ---------------------------------------------------------------------------
// K3: routed channel-group gather (simple measured version).
// Block = (batch, 64-pixel tile), 128 threads x 8 independent float4 copies.
// ---------------------------------------------------------------------------
__global__ __launch_bounds__(128) void gather_kernel(const float4* __restrict__ in4,
                                                     float4* __restrict__ out4) {
    const int b = blockIdx.x;
    const int r = g_route[b];
    const size_t base_pix = (size_t)b * (HH * WW) + (size_t)blockIdx.y * 64;
    const float4* src = in4 + base_pix * (CC / 4) + r * (RW / 4);
    float4* dst = out4 + base_pix * (RW / 4);

    const int t = threadIdx.x;
#pragma unroll
    for (int k = 0; k < 8; k++) {
        const int item = t + k * 128;      // 0..1023 = 64 pixels x 16 float4
        const int p = item >> 4;
        const int j = item & 15;
        dst[item] = src[(size_t)p * (CC / 4) + j];
    }
}

// ---------------------------------------------------------------------------
extern "C" void kernel_launch(void* const* d_in, const int* in_sizes, int n_in,
                              void* d_out, int out_size) {
    const float* in     = (const float*)d_in[0];
    const float* conv_w = (const float*)d_in[1];
    const float* conv_b = (const float*)d_in[2];
    const float* fc_w   = (const float*)d_in[3];
    const float* fc_b   = (const float*)d_in[4];

    float* out        = (float*)d_out;
    float* out_logits = out + (size_t)BB * HH * WW * RW;  // x first, then logits

    patch_route_kernel<<<NW2B + NPATCH, 256>>>(in, conv_w, conv_b, fc_w, fc_b,
                                               out_logits);
    gather_kernel<<<dim3(BB, HH * WW / 64), 128>>>((const float4*)in, (float4*)out);
}